// round 7
// baseline (speedup 1.0000x reference)
#include <cuda_runtime.h>
#include <cuda_bf16.h>
#include <cstdint>

// ---------------------------------------------------------------------------
// Problem constants
// ---------------------------------------------------------------------------
#define Bsz  8
#define Sq   4096
#define Ltxt 77
#define Limg 16
#define Dm   1280
#define Cm   2048
#define Hh   20
#define DHd  64
#define Mbig (Bsz * Sq)          // 32768
#define Mtxt (Bsz * Ltxt)        // 616
#define Mimg (Bsz * Limg)        // 128

// ---------------------------------------------------------------------------
// Scratch (__device__ globals; no allocation allowed)
// ---------------------------------------------------------------------------
__device__ float g_Q[(size_t)Mbig * Dm];
__device__ float g_Ktxt[Mtxt * Dm];
__device__ float g_Vtxt[Mtxt * Dm];
__device__ float g_Kid [Mimg * Dm];
__device__ float g_Vid [Mimg * Dm];
__device__ float g_Khair[Mimg * Dm];
__device__ float g_Vhair[Mimg * Dm];

// bf16 hi/lo splits of activations (A operands, [M][K] row-major)
__device__ __nv_bfloat16 g_Ahi[(size_t)Mbig * Dm], g_Alo[(size_t)Mbig * Dm];
__device__ __nv_bfloat16 g_Ohi[(size_t)Mbig * Dm], g_Olo[(size_t)Mbig * Dm];
__device__ __nv_bfloat16 g_Thi[(size_t)Mtxt * Cm], g_Tlo[(size_t)Mtxt * Cm];
__device__ __nv_bfloat16 g_Ihi[(size_t)Mimg * Cm], g_Ilo[(size_t)Mimg * Cm];
__device__ __nv_bfloat16 g_Hhi[(size_t)Mimg * Cm], g_Hlo[(size_t)Mimg * Cm];

// transposed + split weights: Wt[n][k] bf16 (B operands)
__device__ __nv_bfloat16 g_WtQ_hi[Dm * Dm],  g_WtQ_lo[Dm * Dm];
__device__ __nv_bfloat16 g_WtO_hi[Dm * Dm],  g_WtO_lo[Dm * Dm];
__device__ __nv_bfloat16 g_WtKV_hi[6][(size_t)Dm * Cm];
__device__ __nv_bfloat16 g_WtKV_lo[6][(size_t)Dm * Cm];

// ---------------------------------------------------------------------------
// Helpers
// ---------------------------------------------------------------------------
__device__ __forceinline__ uint32_t smem_u32(const void* p) {
    uint32_t a;
    asm("{ .reg .u64 t; cvta.to.shared.u64 t, %1; cvt.u32.u64 %0, t; }"
        : "=r"(a) : "l"(p));
    return a;
}
__device__ __forceinline__ void split1(float v, __nv_bfloat16& h, __nv_bfloat16& l) {
    h = __float2bfloat16_rn(v);
    l = __float2bfloat16_rn(v - __bfloat162float(h));
}
__device__ __forceinline__ void cpa16(uint32_t dst, const void* src, bool p) {
    int sz = p ? 16 : 0;
    asm volatile("cp.async.cg.shared.global [%0], [%1], 16, %2;"
                 :: "r"(dst), "l"(src), "r"(sz));
}
__device__ __forceinline__ void ldm4(uint32_t* r, uint32_t addr) {
    asm volatile("ldmatrix.sync.aligned.m8n8.x4.shared.b16 {%0,%1,%2,%3}, [%4];"
                 : "=r"(r[0]), "=r"(r[1]), "=r"(r[2]), "=r"(r[3]) : "r"(addr));
}
__device__ __forceinline__ void mma16816(float* d, const uint32_t* a,
                                         uint32_t b0, uint32_t b1) {
    asm volatile(
        "mma.sync.aligned.m16n8k16.row.col.f32.bf16.bf16.f32 "
        "{%0,%1,%2,%3}, {%4,%5,%6,%7}, {%8,%9}, {%0,%1,%2,%3};"
        : "+f"(d[0]), "+f"(d[1]), "+f"(d[2]), "+f"(d[3])
        : "r"(a[0]), "r"(a[1]), "r"(a[2]), "r"(a[3]), "r"(b0), "r"(b1));
}
// packed f32x2 (sm_103a)
__device__ __forceinline__ unsigned long long pk2(float lo, float hi) {
    unsigned long long r;
    asm("mov.b64 %0, {%1, %2};" : "=l"(r) : "f"(lo), "f"(hi));
    return r;
}
__device__ __forceinline__ void fma2(unsigned long long& d,
                                     unsigned long long a,
                                     unsigned long long b) {
    asm("fma.rn.f32x2 %0, %1, %2, %0;" : "+l"(d) : "l"(a), "l"(b));
}
__device__ __forceinline__ void upk2(unsigned long long v, float& lo, float& hi) {
    asm("mov.b64 {%0, %1}, %2;" : "=f"(lo), "=f"(hi) : "l"(v));
}

// ---------------------------------------------------------------------------
// Weight transpose + split:  W[K,N=1280] fp32  ->  Wt_hi/lo[N,K] bf16
// ---------------------------------------------------------------------------
__global__ void __launch_bounds__(256)
transpose_split_kernel(const float* __restrict__ Wq, const float* __restrict__ Wo,
                       const float* __restrict__ Wk,  const float* __restrict__ Wv,
                       const float* __restrict__ Wki, const float* __restrict__ Wvi,
                       const float* __restrict__ Wkh, const float* __restrict__ Wvh) {
    const float* W; __nv_bfloat16* Hi; __nv_bfloat16* Lo; int K;
    switch (blockIdx.z) {
        case 0: W = Wq;  Hi = g_WtQ_hi;     Lo = g_WtQ_lo;     K = Dm; break;
        case 1: W = Wo;  Hi = g_WtO_hi;     Lo = g_WtO_lo;     K = Dm; break;
        case 2: W = Wk;  Hi = g_WtKV_hi[0]; Lo = g_WtKV_lo[0]; K = Cm; break;
        case 3: W = Wv;  Hi = g_WtKV_hi[1]; Lo = g_WtKV_lo[1]; K = Cm; break;
        case 4: W = Wki; Hi = g_WtKV_hi[2]; Lo = g_WtKV_lo[2]; K = Cm; break;
        case 5: W = Wvi; Hi = g_WtKV_hi[3]; Lo = g_WtKV_lo[3]; K = Cm; break;
        case 6: W = Wkh; Hi = g_WtKV_hi[4]; Lo = g_WtKV_lo[4]; K = Cm; break;
        default:W = Wvh; Hi = g_WtKV_hi[5]; Lo = g_WtKV_lo[5]; K = Cm; break;
    }
    int k0 = blockIdx.y * 32;
    if (k0 >= K) return;
    int n0 = blockIdx.x * 32;

    __shared__ float ts[32][33];
    int tx = threadIdx.x & 31;
    int ty = threadIdx.x >> 5;
#pragma unroll
    for (int j = 0; j < 4; j++)
        ts[ty + j * 8][tx] = W[(size_t)(k0 + ty + j * 8) * Dm + n0 + tx];
    __syncthreads();
#pragma unroll
    for (int j = 0; j < 4; j++) {
        int nn = ty + j * 8;
        __nv_bfloat16 h, l;
        split1(ts[tx][nn], h, l);
        size_t off = (size_t)(n0 + nn) * K + k0 + tx;
        Hi[off] = h;
        Lo[off] = l;
    }
}

// ---------------------------------------------------------------------------
// Activation split:  fp32 [n] -> hi/lo bf16
// ---------------------------------------------------------------------------
__global__ void __launch_bounds__(256)
split_inputs_kernel(const float* __restrict__ hidden, const float* __restrict__ text,
                    const float* __restrict__ ids,    const float* __restrict__ hair) {
    const float* src; __nv_bfloat16* hi; __nv_bfloat16* lo; size_t n;
    switch (blockIdx.z) {
        case 0:  src = hidden; hi = g_Ahi; lo = g_Alo; n = (size_t)Mbig * Dm; break;
        case 1:  src = text;   hi = g_Thi; lo = g_Tlo; n = (size_t)Mtxt * Cm; break;
        case 2:  src = ids;    hi = g_Ihi; lo = g_Ilo; n = (size_t)Mimg * Cm; break;
        default: src = hair;   hi = g_Hhi; lo = g_Hlo; n = (size_t)Mimg * Cm; break;
    }
    size_t n4 = n >> 2;
    for (size_t i = (size_t)blockIdx.x * 256 + threadIdx.x; i < n4;
         i += (size_t)gridDim.x * 256) {
        float4 v = ((const float4*)src)[i];
        __nv_bfloat16 h0, h1, h2, h3, l0, l1, l2, l3;
        split1(v.x, h0, l0); split1(v.y, h1, l1);
        split1(v.z, h2, l2); split1(v.w, h3, l3);
        __nv_bfloat162 ha = __halves2bfloat162(h0, h1);
        __nv_bfloat162 hb = __halves2bfloat162(h2, h3);
        __nv_bfloat162 la = __halves2bfloat162(l0, l1);
        __nv_bfloat162 lb = __halves2bfloat162(l2, l3);
        uint2 hp, lp;
        hp.x = *(uint32_t*)&ha; hp.y = *(uint32_t*)&hb;
        lp.x = *(uint32_t*)&la; lp.y = *(uint32_t*)&lb;
        *(uint2*)(hi + i * 4) = hp;
        *(uint2*)(lo + i * 4) = lp;
    }
}

// ---------------------------------------------------------------------------
// Warp-MMA bf16 3-pass GEMM body (unchanged — near legacy-HMMA ceiling)
// ---------------------------------------------------------------------------
#define BM 128
#define BN 128
#define BKB 32
#define ROWB 80
#define A_HI 0
#define A_LO 10240
#define B_HI 20480
#define B_LO 30720
#define STAGE_B 40960
#define GSMEM (2 * STAGE_B)

__device__ __forceinline__ void mma_gemm_body(
    const __nv_bfloat16* __restrict__ Ahi, const __nv_bfloat16* __restrict__ Alo,
    const __nv_bfloat16* __restrict__ Bhi, const __nv_bfloat16* __restrict__ Blo,
    const float* __restrict__ bias, float* __restrict__ C,
    int M, int K, int bx, int by)
{
    extern __shared__ __align__(128) char smem[];
    const int tid  = threadIdx.x;
    const int lane = tid & 31;
    const int wid  = tid >> 5;
    const int wm   = wid & 1;
    const int wn   = wid >> 1;
    const int row0 = by * BM;
    const int col0 = bx * BN;
    const int nch  = K / BKB;

    float acc[4][4][4];
#pragma unroll
    for (int a = 0; a < 4; a++)
#pragma unroll
        for (int b = 0; b < 4; b++)
#pragma unroll
            for (int d = 0; d < 4; d++) acc[a][b][d] = 0.f;

    auto ld_stage = [&](int c, int s) {
        uint32_t base = smem_u32(smem + s * STAGE_B);
        int k0 = c * BKB;
#pragma unroll
        for (int i = 0; i < 2; i++) {
            int lin = i * 256 + tid;
            int r   = lin >> 2;
            int sg  = lin & 3;
            uint32_t d = base + r * ROWB + sg * 16;
            int grow = row0 + r;
            bool p = grow < M;
            int ga = p ? grow : (M - 1);
            size_t aoff = (size_t)ga * K + k0 + sg * 8;
            cpa16(d + A_HI, Ahi + aoff, p);
            cpa16(d + A_LO, Alo + aoff, p);
            size_t boff = (size_t)(col0 + r) * K + k0 + sg * 8;
            cpa16(d + B_HI, Bhi + boff, true);
            cpa16(d + B_LO, Blo + boff, true);
        }
    };

    auto compute = [&](int s) {
        uint32_t sb = smem_u32(smem + s * STAGE_B);
        uint32_t aB = sb + (wm * 64) * ROWB;
        uint32_t bB = sb + B_HI + (wn * 32) * ROWB;
        uint32_t lrow  = lane & 15;
        uint32_t lhalf = (lane >> 4) * 16;
#pragma unroll
        for (int ks = 0; ks < 2; ks++) {
            uint32_t bh[2][4], bl[2][4];
#pragma unroll
            for (int ng = 0; ng < 2; ng++) {
                uint32_t ad = bB + (ng * 16 + lrow) * ROWB + ks * 32 + lhalf;
                ldm4(bh[ng], ad);
                ldm4(bl[ng], ad + 10240);
            }
#pragma unroll
            for (int mt = 0; mt < 4; mt++) {
                uint32_t ah[4], al[4];
                uint32_t ad = aB + (mt * 16 + lrow) * ROWB + ks * 32 + lhalf;
                ldm4(ah, ad);
                ldm4(al, ad + 10240);
#pragma unroll
                for (int j = 0; j < 4; j++) {
                    int ng = j >> 1, q = j & 1;
                    mma16816(acc[mt][j], ah, bh[ng][q], bh[ng][q + 2]);
                    mma16816(acc[mt][j], ah, bl[ng][q], bl[ng][q + 2]);
                    mma16816(acc[mt][j], al, bh[ng][q], bh[ng][q + 2]);
                }
            }
        }
    };

    ld_stage(0, 0);
    asm volatile("cp.async.commit_group;" ::: "memory");
    for (int c = 0; c < nch; c++) {
        int s = c & 1;
        if (c + 1 < nch) {
            ld_stage(c + 1, s ^ 1);
            asm volatile("cp.async.commit_group;" ::: "memory");
            asm volatile("cp.async.wait_group 1;" ::: "memory");
        } else {
            asm volatile("cp.async.wait_group 0;" ::: "memory");
        }
        __syncthreads();
        compute(s);
        __syncthreads();
    }

    const int tg = lane >> 2, tq = lane & 3;
#pragma unroll
    for (int mt = 0; mt < 4; mt++) {
        int r0 = row0 + wm * 64 + mt * 16 + tg;
        int r1 = r0 + 8;
#pragma unroll
        for (int j = 0; j < 4; j++) {
            int col = col0 + wn * 32 + j * 8 + tq * 2;
            float b0 = 0.f, b1 = 0.f;
            if (bias) { b0 = bias[col]; b1 = bias[col + 1]; }
            if (r0 < M)
                *(float2*)(C + (size_t)r0 * Dm + col) =
                    make_float2(acc[mt][j][0] + b0, acc[mt][j][1] + b1);
            if (r1 < M)
                *(float2*)(C + (size_t)r1 * Dm + col) =
                    make_float2(acc[mt][j][2] + b0, acc[mt][j][3] + b1);
        }
    }
}

// Merged Q + 6xKV GEMM
__global__ void __launch_bounds__(256, 2)
gemm_qkv_kernel() {
    int y = blockIdx.y;
    if (y < 256) {
        mma_gemm_body(g_Ahi, g_Alo, g_WtQ_hi, g_WtQ_lo, nullptr, g_Q,
                      Mbig, Dm, blockIdx.x, y);
        return;
    }
    int yy = y - 256;
    const __nv_bfloat16 *ah, *al; float* Cc; int M, z, by;
    if (yy < 5)       { z = 0; by = yy;     ah = g_Thi; al = g_Tlo; Cc = g_Ktxt;  M = Mtxt; }
    else if (yy < 10) { z = 1; by = yy - 5; ah = g_Thi; al = g_Tlo; Cc = g_Vtxt;  M = Mtxt; }
    else if (yy == 10){ z = 2; by = 0;      ah = g_Ihi; al = g_Ilo; Cc = g_Kid;   M = Mimg; }
    else if (yy == 11){ z = 3; by = 0;      ah = g_Ihi; al = g_Ilo; Cc = g_Vid;   M = Mimg; }
    else if (yy == 12){ z = 4; by = 0;      ah = g_Hhi; al = g_Hlo; Cc = g_Khair; M = Mimg; }
    else              { z = 5; by = 0;      ah = g_Hhi; al = g_Hlo; Cc = g_Vhair; M = Mimg; }
    mma_gemm_body(ah, al, g_WtKV_hi[z], g_WtKV_lo[z], nullptr, Cc,
                  M, Cm, blockIdx.x, by);
}

__global__ void __launch_bounds__(256, 2)
gemm_out_kernel(const float* __restrict__ bo, float* __restrict__ out) {
    mma_gemm_body(g_Ohi, g_Olo, g_WtO_hi, g_WtO_lo, bo, out,
                  Mbig, Dm, blockIdx.x, blockIdx.y);
}

// ---------------------------------------------------------------------------
// Fused attention v3: register-resident Q, broadcast-only K reads,
// txt branch + merged (id|hair) branch.
// ---------------------------------------------------------------------------
template <int NM>
__device__ __forceinline__ void attn_scores3(const ulonglong2* __restrict__ qr,
                                             const float* __restrict__ KV,
                                             float (*Ps)[81],
                                             int lane, int w) {
    unsigned long long acc[NM];
#pragma unroll
    for (int m = 0; m < NM; m++) acc[m] = 0ull;
#pragma unroll 4
    for (int d4 = 0; d4 < 16; d4++) {
        ulonglong2 qp = qr[d4];
#pragma unroll
        for (int m = 0; m < NM; m++) {
            ulonglong2 kp = *(const ulonglong2*)&KV[(w + 8 * m) * 64 + d4 * 4]; // broadcast
            fma2(acc[m], qp.x, kp.x);
            fma2(acc[m], qp.y, kp.y);
        }
    }
    const float scale = 0.125f;
#pragma unroll
    for (int m = 0; m < NM; m++) {
        float lo, hi;
        upk2(acc[m], lo, hi);
        Ps[lane][w + 8 * m] = (lo + hi) * scale;
    }
}

__global__ void __launch_bounds__(256) attn_kernel() {
    __shared__ __align__(16) float Qs[32][68];
    __shared__ __align__(16) float KV[80 * 64];
    __shared__ float Ps[32][81];

    const int tid  = threadIdx.x;
    const int lane = tid & 31;
    const int w    = tid >> 5;
    const int q0   = blockIdx.x * 32;
    const int bh   = blockIdx.y;
    const int b    = bh / Hh;
    const int h    = bh % Hh;

    // stage Q tile [32 x 64]
    {
        int q  = tid >> 3;
        int dd = (tid & 7) * 8;
        const float* src = g_Q + ((size_t)(b * Sq + q0 + q)) * Dm + h * DHd + dd;
        *(float4*)&Qs[q][dd]     = *(const float4*)src;
        *(float4*)&Qs[q][dd + 4] = *(const float4*)(src + 4);
    }
    __syncthreads();

    // pull this thread's q-row (q = lane) into registers, packed f32x2
    ulonglong2 qr[16];
#pragma unroll
    for (int d4 = 0; d4 < 16; d4++)
        qr[d4] = *(const ulonglong2*)&Qs[lane][d4 * 4];

    unsigned long long o2[4] = {0ull, 0ull, 0ull, 0ull};

    // ===================== branch 0: text (L=77) =====================
    {
        const int L = Ltxt;
        // K tile, zero-padded to 80 rows
        for (int i = tid; i < 80 * 16; i += 256) {
            int l = i >> 4;
            int c = (i & 15) * 4;
            float4 v = make_float4(0.f, 0.f, 0.f, 0.f);
            if (l < L)
                v = *(const float4*)(g_Ktxt + ((size_t)(b * L + l)) * Dm + h * DHd + c);
            *(float4*)&KV[l * 64 + c] = v;
        }
        __syncthreads();

        attn_scores3<10>(qr, KV, Ps, lane, w);
        __syncthreads();

        // softmax over j < 77 (8 threads per row), then V load (independent)
        {
            int q   = tid >> 3;
            int sub = tid & 7;
            float mx = -1e30f;
            for (int j = sub; j < L; j += 8) mx = fmaxf(mx, Ps[q][j]);
#pragma unroll
            for (int off = 1; off < 8; off <<= 1)
                mx = fmaxf(mx, __shfl_xor_sync(0xffffffffu, mx, off));
            float s = 0.f;
            for (int j = sub; j < L; j += 8) {
                float e = __expf(Ps[q][j] - mx);
                Ps[q][j] = e;
                s += e;
            }
#pragma unroll
            for (int off = 1; off < 8; off <<= 1)
                s += __shfl_xor_sync(0xffffffffu, s, off);
            float inv = 1.f / s;
            for (int j = sub; j < L; j += 8) Ps[q][j] *= inv;
        }
        for (int i = tid; i < L * 16; i += 256) {
            int l = i >> 4;
            int c = (i & 15) * 4;
            *(float4*)&KV[l * 64 + c] =
                *(const float4*)(g_Vtxt + ((size_t)(b * L + l)) * Dm + h * DHd + c);
        }
        __syncthreads();

        // PV
        {
            int q  = tid & 31;
            int dw = (tid >> 5) * 8;
            for (int j = 0; j < L; j++) {
                unsigned long long pp = pk2(Ps[q][j], Ps[q][j]);
                ulonglong2 v0 = *(const ulonglong2*)&KV[j * 64 + dw];
                ulonglong2 v1 = *(const ulonglong2*)&KV[j * 64 + dw + 4];
                fma2(o2[0], pp, v0.x);
                fma2(o2[1], pp, v0.y);
                fma2(o2[2], pp, v1.x);
                fma2(o2[3], pp, v1.y);
            }
        }
        __syncthreads();
    }

    // ============== branch 1: merged id (rows 0-15) | hair (16-31) ==============
    {
        // K: id rows then hair rows
        for (int i = tid; i < 32 * 16; i += 256) {
            int l = i >> 4;
            int c = (i & 15) * 4;
            const float* src = (l < 16)
                ? (g_Kid   + ((size_t)(b * Limg + l)) * Dm + h * DHd + c)
                : (g_Khair + ((size_t)(b * Limg + (l - 16))) * Dm + h * DHd + c);
            *(float4*)&KV[l * 64 + c] = *(const float4*)src;
        }
        __syncthreads();

        attn_scores3<4>(qr, KV, Ps, lane, w);
        __syncthreads();

        // two independent half-softmaxes (j in [0,16) and [16,32))
        {
            int q   = tid >> 3;
            int sub = tid & 7;
#pragma unroll
            for (int hf = 0; hf < 2; hf++) {
                int j0 = hf * 16;
                float a = Ps[q][j0 + sub];
                float bb = Ps[q][j0 + sub + 8];
                float mx = fmaxf(a, bb);
#pragma unroll
                for (int off = 1; off < 8; off <<= 1)
                    mx = fmaxf(mx, __shfl_xor_sync(0xffffffffu, mx, off));
                float e0 = __expf(a - mx);
                float e1 = __expf(bb - mx);
                float s = e0 + e1;
#pragma unroll
                for (int off = 1; off < 8; off <<= 1)
                    s += __shfl_xor_sync(0xffffffffu, s, off);
                float inv = 1.f / s;
                Ps[q][j0 + sub]     = e0 * inv;
                Ps[q][j0 + sub + 8] = e1 * inv;
            }
        }
        // V: id rows then hair rows (overwrites KV; scores readers done)
        for (int i = tid; i < 32 * 16; i += 256) {
            int l = i >> 4;
            int c = (i & 15) * 4;
            const float* src = (l < 16)
                ? (g_Vid   + ((size_t)(b * Limg + l)) * Dm + h * DHd + c)
                : (g_Vhair + ((size_t)(b * Limg + (l - 16))) * Dm + h * DHd + c);
            *(float4*)&KV[l * 64 + c] = *(const float4*)src;
        }
        __syncthreads();

        // PV over 32 rows: concatenated normalized P == sum of both branches
        {
            int q  = tid & 31;
            int dw = (tid >> 5) * 8;
#pragma unroll 4
            for (int j = 0; j < 32; j++) {
                unsigned long long pp = pk2(Ps[q][j], Ps[q][j]);
                ulonglong2 v0 = *(const ulonglong2*)&KV[j * 64 + dw];
                ulonglong2 v1 = *(const ulonglong2*)&KV[j * 64 + dw + 4];
                fma2(o2[0], pp, v0.x);
                fma2(o2[1], pp, v0.y);
                fma2(o2[2], pp, v1.x);
                fma2(o2[3], pp, v1.y);
            }
        }
    }

    // epilogue: unpack, split to hi/lo bf16 (feeds out-GEMM A operand)
    {
        float o[8];
#pragma unroll
        for (int i = 0; i < 4; i++) upk2(o2[i], o[2 * i], o[2 * i + 1]);
        int q  = tid & 31;
        int dw = (tid >> 5) * 8;
        __nv_bfloat16 hv[8], lv[8];
#pragma unroll
        for (int i = 0; i < 8; i++) split1(o[i], hv[i], lv[i]);
        uint4 hp, lp;
        {
            __nv_bfloat162 a0 = __halves2bfloat162(hv[0], hv[1]);
            __nv_bfloat162 a1 = __halves2bfloat162(hv[2], hv[3]);
            __nv_bfloat162 a2 = __halves2bfloat162(hv[4], hv[5]);
            __nv_bfloat162 a3 = __halves2bfloat162(hv[6], hv[7]);
            hp.x = *(uint32_t*)&a0; hp.y = *(uint32_t*)&a1;
            hp.z = *(uint32_t*)&a2; hp.w = *(uint32_t*)&a3;
            __nv_bfloat162 c0 = __halves2bfloat162(lv[0], lv[1]);
            __nv_bfloat162 c1 = __halves2bfloat162(lv[2], lv[3]);
            __nv_bfloat162 c2 = __halves2bfloat162(lv[4], lv[5]);
            __nv_bfloat162 c3 = __halves2bfloat162(lv[6], lv[7]);
            lp.x = *(uint32_t*)&c0; lp.y = *(uint32_t*)&c1;
            lp.z = *(uint32_t*)&c2; lp.w = *(uint32_t*)&c3;
        }
        size_t off = ((size_t)(b * Sq + q0 + q)) * Dm + h * DHd + dw;
        *(uint4*)(g_Ohi + off) = hp;
        *(uint4*)(g_Olo + off) = lp;
    }
}

// ---------------------------------------------------------------------------
// kernel_launch
// ---------------------------------------------------------------------------
extern "C" void kernel_launch(void* const* d_in, const int* in_sizes, int n_in,
                              void* d_out, int out_size) {
    const float* hidden = (const float*)d_in[0];
    const float* text   = (const float*)d_in[1];
    const float* ids    = (const float*)d_in[2];
    const float* hair   = (const float*)d_in[3];
    const float* Wq     = (const float*)d_in[4];
    const float* Wk     = (const float*)d_in[5];
    const float* Wv     = (const float*)d_in[6];
    const float* Wo     = (const float*)d_in[7];
    const float* bo     = (const float*)d_in[8];
    const float* Wk_id  = (const float*)d_in[9];
    const float* Wv_id  = (const float*)d_in[10];
    const float* Wk_h   = (const float*)d_in[11];
    const float* Wv_h   = (const float*)d_in[12];
    float* out = (float*)d_out;

    cudaFuncSetAttribute(gemm_qkv_kernel, cudaFuncAttributeMaxDynamicSharedMemorySize, GSMEM);
    cudaFuncSetAttribute(gemm_out_kernel, cudaFuncAttributeMaxDynamicSharedMemorySize, GSMEM);

    // 1) transpose + split all 8 weight matrices -> Wt[n][k] hi/lo
    transpose_split_kernel<<<dim3(Dm / 32, Cm / 32, 8), 256>>>(
        Wq, Wo, Wk, Wv, Wk_id, Wv_id, Wk_h, Wv_h);

    // 2) split activations -> hi/lo bf16
    split_inputs_kernel<<<dim3(8192, 1, 4), 256>>>(hidden, text, ids, hair);

    // 3) Q GEMM + all six K/V projections in ONE launch
    gemm_qkv_kernel<<<dim3(Dm / BN, 256 + 14), 256, GSMEM>>>();

    // 4) fused attention (txt + merged id|hair) -> g_Ohi/g_Olo
    attn_kernel<<<dim3(Sq / 32, Bsz * Hh), 256>>>();

    // 5) out = O @ Wo + bo
    gemm_out_kernel<<<dim3(Dm / BN, Mbig / BM), 256, GSMEM>>>(bo, out);
}

// round 8
// speedup vs baseline: 1.2755x; 1.2755x over previous
#include <cuda_runtime.h>
#include <cuda_bf16.h>
#include <cstdint>

// ---------------------------------------------------------------------------
// Problem constants
// ---------------------------------------------------------------------------
#define Bsz  8
#define Sq   4096
#define Ltxt 77
#define Limg 16
#define Dm   1280
#define Cm   2048
#define Hh   20
#define DHd  64
#define Mbig (Bsz * Sq)          // 32768
#define Mtxt (Bsz * Ltxt)        // 616
#define Mimg (Bsz * Limg)        // 128

// ---------------------------------------------------------------------------
// Scratch (__device__ globals; no allocation allowed)
// ---------------------------------------------------------------------------
// bf16 hi/lo splits of activations (A operands, [M][K] row-major)
__device__ __nv_bfloat16 g_Ahi[(size_t)Mbig * Dm], g_Alo[(size_t)Mbig * Dm];
__device__ __nv_bfloat16 g_Ohi[(size_t)Mbig * Dm], g_Olo[(size_t)Mbig * Dm];
__device__ __nv_bfloat16 g_Thi[(size_t)Mtxt * Cm], g_Tlo[(size_t)Mtxt * Cm];
__device__ __nv_bfloat16 g_Ihi[(size_t)Mimg * Cm], g_Ilo[(size_t)Mimg * Cm];
__device__ __nv_bfloat16 g_Hhi[(size_t)Mimg * Cm], g_Hlo[(size_t)Mimg * Cm];

// Q and K/V now live as bf16 hi/lo (written by GEMM epilogues)
__device__ __nv_bfloat16 g_Qhi[(size_t)Mbig * Dm], g_Qlo[(size_t)Mbig * Dm];
// z: 0 Ktxt, 1 Vtxt, 2 Kid, 3 Vid, 4 Khair, 5 Vhair
__device__ __nv_bfloat16 g_KVhi[6][(size_t)Mtxt * Dm];
__device__ __nv_bfloat16 g_KVlo[6][(size_t)Mtxt * Dm];

// transposed + split weights: Wt[n][k] bf16 (B operands)
__device__ __nv_bfloat16 g_WtQ_hi[Dm * Dm],  g_WtQ_lo[Dm * Dm];
__device__ __nv_bfloat16 g_WtO_hi[Dm * Dm],  g_WtO_lo[Dm * Dm];
__device__ __nv_bfloat16 g_WtKV_hi[6][(size_t)Dm * Cm];
__device__ __nv_bfloat16 g_WtKV_lo[6][(size_t)Dm * Cm];

// ---------------------------------------------------------------------------
// Helpers
// ---------------------------------------------------------------------------
__device__ __forceinline__ uint32_t smem_u32(const void* p) {
    uint32_t a;
    asm("{ .reg .u64 t; cvta.to.shared.u64 t, %1; cvt.u32.u64 %0, t; }"
        : "=r"(a) : "l"(p));
    return a;
}
__device__ __forceinline__ void split1(float v, __nv_bfloat16& h, __nv_bfloat16& l) {
    h = __float2bfloat16_rn(v);
    l = __float2bfloat16_rn(v - __bfloat162float(h));
}
// split two floats -> packed hi bf16x2 + packed lo bf16x2 (lo half = first elem)
__device__ __forceinline__ void sp2(float v0, float v1, uint32_t& h, uint32_t& l) {
    __nv_bfloat16 b0 = __float2bfloat16_rn(v0);
    __nv_bfloat16 b1 = __float2bfloat16_rn(v1);
    __nv_bfloat162 hh = __halves2bfloat162(b0, b1);
    h = *(uint32_t*)&hh;
    __nv_bfloat162 ll = __halves2bfloat162(
        __float2bfloat16_rn(v0 - __bfloat162float(b0)),
        __float2bfloat16_rn(v1 - __bfloat162float(b1)));
    l = *(uint32_t*)&ll;
}
__device__ __forceinline__ void cpa16(uint32_t dst, const void* src, bool p) {
    int sz = p ? 16 : 0;
    asm volatile("cp.async.cg.shared.global [%0], [%1], 16, %2;"
                 :: "r"(dst), "l"(src), "r"(sz));
}
__device__ __forceinline__ void ldm4(uint32_t* r, uint32_t addr) {
    asm volatile("ldmatrix.sync.aligned.m8n8.x4.shared.b16 {%0,%1,%2,%3}, [%4];"
                 : "=r"(r[0]), "=r"(r[1]), "=r"(r[2]), "=r"(r[3]) : "r"(addr));
}
__device__ __forceinline__ void ldm4t(uint32_t* r, uint32_t addr) {
    asm volatile("ldmatrix.sync.aligned.m8n8.x4.trans.shared.b16 {%0,%1,%2,%3}, [%4];"
                 : "=r"(r[0]), "=r"(r[1]), "=r"(r[2]), "=r"(r[3]) : "r"(addr));
}
__device__ __forceinline__ void mma16816(float* d, const uint32_t* a,
                                         uint32_t b0, uint32_t b1) {
    asm volatile(
        "mma.sync.aligned.m16n8k16.row.col.f32.bf16.bf16.f32 "
        "{%0,%1,%2,%3}, {%4,%5,%6,%7}, {%8,%9}, {%0,%1,%2,%3};"
        : "+f"(d[0]), "+f"(d[1]), "+f"(d[2]), "+f"(d[3])
        : "r"(a[0]), "r"(a[1]), "r"(a[2]), "r"(a[3]), "r"(b0), "r"(b1));
}

// ---------------------------------------------------------------------------
// Weight transpose + split:  W[K,N=1280] fp32  ->  Wt_hi/lo[N,K] bf16
// ---------------------------------------------------------------------------
__global__ void __launch_bounds__(256)
transpose_split_kernel(const float* __restrict__ Wq, const float* __restrict__ Wo,
                       const float* __restrict__ Wk,  const float* __restrict__ Wv,
                       const float* __restrict__ Wki, const float* __restrict__ Wvi,
                       const float* __restrict__ Wkh, const float* __restrict__ Wvh) {
    const float* W; __nv_bfloat16* Hi; __nv_bfloat16* Lo; int K;
    switch (blockIdx.z) {
        case 0: W = Wq;  Hi = g_WtQ_hi;     Lo = g_WtQ_lo;     K = Dm; break;
        case 1: W = Wo;  Hi = g_WtO_hi;     Lo = g_WtO_lo;     K = Dm; break;
        case 2: W = Wk;  Hi = g_WtKV_hi[0]; Lo = g_WtKV_lo[0]; K = Cm; break;
        case 3: W = Wv;  Hi = g_WtKV_hi[1]; Lo = g_WtKV_lo[1]; K = Cm; break;
        case 4: W = Wki; Hi = g_WtKV_hi[2]; Lo = g_WtKV_lo[2]; K = Cm; break;
        case 5: W = Wvi; Hi = g_WtKV_hi[3]; Lo = g_WtKV_lo[3]; K = Cm; break;
        case 6: W = Wkh; Hi = g_WtKV_hi[4]; Lo = g_WtKV_lo[4]; K = Cm; break;
        default:W = Wvh; Hi = g_WtKV_hi[5]; Lo = g_WtKV_lo[5]; K = Cm; break;
    }
    int k0 = blockIdx.y * 32;
    if (k0 >= K) return;
    int n0 = blockIdx.x * 32;

    __shared__ float ts[32][33];
    int tx = threadIdx.x & 31;
    int ty = threadIdx.x >> 5;
#pragma unroll
    for (int j = 0; j < 4; j++)
        ts[ty + j * 8][tx] = W[(size_t)(k0 + ty + j * 8) * Dm + n0 + tx];
    __syncthreads();
#pragma unroll
    for (int j = 0; j < 4; j++) {
        int nn = ty + j * 8;
        __nv_bfloat16 h, l;
        split1(ts[tx][nn], h, l);
        size_t off = (size_t)(n0 + nn) * K + k0 + tx;
        Hi[off] = h;
        Lo[off] = l;
    }
}

// ---------------------------------------------------------------------------
// Activation split:  fp32 [n] -> hi/lo bf16
// ---------------------------------------------------------------------------
__global__ void __launch_bounds__(256)
split_inputs_kernel(const float* __restrict__ hidden, const float* __restrict__ text,
                    const float* __restrict__ ids,    const float* __restrict__ hair) {
    const float* src; __nv_bfloat16* hi; __nv_bfloat16* lo; size_t n;
    switch (blockIdx.z) {
        case 0:  src = hidden; hi = g_Ahi; lo = g_Alo; n = (size_t)Mbig * Dm; break;
        case 1:  src = text;   hi = g_Thi; lo = g_Tlo; n = (size_t)Mtxt * Cm; break;
        case 2:  src = ids;    hi = g_Ihi; lo = g_Ilo; n = (size_t)Mimg * Cm; break;
        default: src = hair;   hi = g_Hhi; lo = g_Hlo; n = (size_t)Mimg * Cm; break;
    }
    size_t n4 = n >> 2;
    for (size_t i = (size_t)blockIdx.x * 256 + threadIdx.x; i < n4;
         i += (size_t)gridDim.x * 256) {
        float4 v = ((const float4*)src)[i];
        __nv_bfloat16 h0, h1, h2, h3, l0, l1, l2, l3;
        split1(v.x, h0, l0); split1(v.y, h1, l1);
        split1(v.z, h2, l2); split1(v.w, h3, l3);
        __nv_bfloat162 ha = __halves2bfloat162(h0, h1);
        __nv_bfloat162 hb = __halves2bfloat162(h2, h3);
        __nv_bfloat162 la = __halves2bfloat162(l0, l1);
        __nv_bfloat162 lb = __halves2bfloat162(l2, l3);
        uint2 hp, lp;
        hp.x = *(uint32_t*)&ha; hp.y = *(uint32_t*)&hb;
        lp.x = *(uint32_t*)&la; lp.y = *(uint32_t*)&lb;
        *(uint2*)(hi + i * 4) = hp;
        *(uint2*)(lo + i * 4) = lp;
    }
}

// ---------------------------------------------------------------------------
// Warp-MMA bf16 3-pass GEMM body. Epilogue: fp32(+bias) if Cf, else split bf16.
// ---------------------------------------------------------------------------
#define BM 128
#define BN 128
#define BKB 32
#define ROWB 80
#define A_HI 0
#define A_LO 10240
#define B_HI 20480
#define B_LO 30720
#define STAGE_B 40960
#define GSMEM (2 * STAGE_B)

__device__ __forceinline__ void mma_gemm_body(
    const __nv_bfloat16* __restrict__ Ahi, const __nv_bfloat16* __restrict__ Alo,
    const __nv_bfloat16* __restrict__ Bhi, const __nv_bfloat16* __restrict__ Blo,
    const float* __restrict__ bias,
    float* __restrict__ Cf,
    __nv_bfloat16* __restrict__ Chi, __nv_bfloat16* __restrict__ Clo,
    int M, int K, int bx, int by)
{
    extern __shared__ __align__(128) char smem[];
    const int tid  = threadIdx.x;
    const int lane = tid & 31;
    const int wid  = tid >> 5;
    const int wm   = wid & 1;
    const int wn   = wid >> 1;
    const int row0 = by * BM;
    const int col0 = bx * BN;
    const int nch  = K / BKB;

    float acc[4][4][4];
#pragma unroll
    for (int a = 0; a < 4; a++)
#pragma unroll
        for (int b = 0; b < 4; b++)
#pragma unroll
            for (int d = 0; d < 4; d++) acc[a][b][d] = 0.f;

    auto ld_stage = [&](int c, int s) {
        uint32_t base = smem_u32(smem + s * STAGE_B);
        int k0 = c * BKB;
#pragma unroll
        for (int i = 0; i < 2; i++) {
            int lin = i * 256 + tid;
            int r   = lin >> 2;
            int sg  = lin & 3;
            uint32_t d = base + r * ROWB + sg * 16;
            int grow = row0 + r;
            bool p = grow < M;
            int ga = p ? grow : (M - 1);
            size_t aoff = (size_t)ga * K + k0 + sg * 8;
            cpa16(d + A_HI, Ahi + aoff, p);
            cpa16(d + A_LO, Alo + aoff, p);
            size_t boff = (size_t)(col0 + r) * K + k0 + sg * 8;
            cpa16(d + B_HI, Bhi + boff, true);
            cpa16(d + B_LO, Blo + boff, true);
        }
    };

    auto compute = [&](int s) {
        uint32_t sb = smem_u32(smem + s * STAGE_B);
        uint32_t aB = sb + (wm * 64) * ROWB;
        uint32_t bB = sb + B_HI + (wn * 32) * ROWB;
        uint32_t lrow  = lane & 15;
        uint32_t lhalf = (lane >> 4) * 16;
#pragma unroll
        for (int ks = 0; ks < 2; ks++) {
            uint32_t bh[2][4], bl[2][4];
#pragma unroll
            for (int ng = 0; ng < 2; ng++) {
                uint32_t ad = bB + (ng * 16 + lrow) * ROWB + ks * 32 + lhalf;
                ldm4(bh[ng], ad);
                ldm4(bl[ng], ad + 10240);
            }
#pragma unroll
            for (int mt = 0; mt < 4; mt++) {
                uint32_t ah[4], al[4];
                uint32_t ad = aB + (mt * 16 + lrow) * ROWB + ks * 32 + lhalf;
                ldm4(ah, ad);
                ldm4(al, ad + 10240);
#pragma unroll
                for (int j = 0; j < 4; j++) {
                    int ng = j >> 1, q = j & 1;
                    mma16816(acc[mt][j], ah, bh[ng][q], bh[ng][q + 2]);
                    mma16816(acc[mt][j], ah, bl[ng][q], bl[ng][q + 2]);
                    mma16816(acc[mt][j], al, bh[ng][q], bh[ng][q + 2]);
                }
            }
        }
    };

    ld_stage(0, 0);
    asm volatile("cp.async.commit_group;" ::: "memory");
    for (int c = 0; c < nch; c++) {
        int s = c & 1;
        if (c + 1 < nch) {
            ld_stage(c + 1, s ^ 1);
            asm volatile("cp.async.commit_group;" ::: "memory");
            asm volatile("cp.async.wait_group 1;" ::: "memory");
        } else {
            asm volatile("cp.async.wait_group 0;" ::: "memory");
        }
        __syncthreads();
        compute(s);
        __syncthreads();
    }

    const int tg = lane >> 2, tq = lane & 3;
#pragma unroll
    for (int mt = 0; mt < 4; mt++) {
        int r0 = row0 + wm * 64 + mt * 16 + tg;
        int r1 = r0 + 8;
#pragma unroll
        for (int j = 0; j < 4; j++) {
            int col = col0 + wn * 32 + j * 8 + tq * 2;
            if (Cf) {
                float b0 = 0.f, b1 = 0.f;
                if (bias) { b0 = bias[col]; b1 = bias[col + 1]; }
                if (r0 < M)
                    *(float2*)(Cf + (size_t)r0 * Dm + col) =
                        make_float2(acc[mt][j][0] + b0, acc[mt][j][1] + b1);
                if (r1 < M)
                    *(float2*)(Cf + (size_t)r1 * Dm + col) =
                        make_float2(acc[mt][j][2] + b0, acc[mt][j][3] + b1);
            } else {
                uint32_t h, l;
                if (r0 < M) {
                    sp2(acc[mt][j][0], acc[mt][j][1], h, l);
                    *(uint32_t*)(Chi + (size_t)r0 * Dm + col) = h;
                    *(uint32_t*)(Clo + (size_t)r0 * Dm + col) = l;
                }
                if (r1 < M) {
                    sp2(acc[mt][j][2], acc[mt][j][3], h, l);
                    *(uint32_t*)(Chi + (size_t)r1 * Dm + col) = h;
                    *(uint32_t*)(Clo + (size_t)r1 * Dm + col) = l;
                }
            }
        }
    }
}

// Merged Q + 6xKV GEMM (all write split bf16 outputs)
__global__ void __launch_bounds__(256, 2)
gemm_qkv_kernel() {
    int y = blockIdx.y;
    if (y < 256) {
        mma_gemm_body(g_Ahi, g_Alo, g_WtQ_hi, g_WtQ_lo, nullptr,
                      nullptr, g_Qhi, g_Qlo, Mbig, Dm, blockIdx.x, y);
        return;
    }
    int yy = y - 256;
    const __nv_bfloat16 *ah, *al; int M, z, by;
    if (yy < 5)       { z = 0; by = yy;     ah = g_Thi; al = g_Tlo; M = Mtxt; }
    else if (yy < 10) { z = 1; by = yy - 5; ah = g_Thi; al = g_Tlo; M = Mtxt; }
    else if (yy == 10){ z = 2; by = 0;      ah = g_Ihi; al = g_Ilo; M = Mimg; }
    else if (yy == 11){ z = 3; by = 0;      ah = g_Ihi; al = g_Ilo; M = Mimg; }
    else if (yy == 12){ z = 4; by = 0;      ah = g_Hhi; al = g_Hlo; M = Mimg; }
    else              { z = 5; by = 0;      ah = g_Hhi; al = g_Hlo; M = Mimg; }
    mma_gemm_body(ah, al, g_WtKV_hi[z], g_WtKV_lo[z], nullptr,
                  nullptr, g_KVhi[z], g_KVlo[z], M, Cm, blockIdx.x, by);
}

__global__ void __launch_bounds__(256, 2)
gemm_out_kernel(const float* __restrict__ bo, float* __restrict__ out) {
    mma_gemm_body(g_Ohi, g_Olo, g_WtO_hi, g_WtO_lo, bo,
                  out, nullptr, nullptr, Mbig, Dm, blockIdx.x, blockIdx.y);
}

// ---------------------------------------------------------------------------
// Flash-style MMA attention. Block = 128 q x one (b,h). 8 warps x 16 q each.
// hi/lo bf16 splits on Q,K,P,V (3-pass mma). Softmax in registers.
// ---------------------------------------------------------------------------
#define AT_QHI 0
#define AT_QLO 18432
#define AT_KHI 36864
#define AT_KLO 48384
#define AT_SMEM 59904
#define KROW 144                 // SMEM row stride bytes (64 bf16 + 8 pad)

__global__ void __launch_bounds__(256) attn_kernel() {
    extern __shared__ __align__(128) char sm[];
    const int tid  = threadIdx.x;
    const int lane = tid & 31;
    const int wid  = tid >> 5;
    const int lrow = lane & 15;
    const int lhalf = (lane >> 4) * 16;
    const int tg = lane >> 2;
    const int tq = lane & 3;
    const int q0 = blockIdx.x * 128;
    const int b  = blockIdx.y / Hh;
    const int hd = blockIdx.y % Hh;
    const int wq0 = wid * 16;

    const uint32_t smb = smem_u32(sm);

    // ---- stage Q hi/lo [128 x 64] ----
    for (int i = tid; i < 1024; i += 256) {
        int row = i >> 3, seg = i & 7;
        size_t off = ((size_t)(b * Sq + q0 + row)) * Dm + hd * 64 + seg * 8;
        *(uint4*)(sm + AT_QHI + row * KROW + seg * 16) = *(const uint4*)(g_Qhi + off);
        *(uint4*)(sm + AT_QLO + row * KROW + seg * 16) = *(const uint4*)(g_Qlo + off);
    }
    __syncthreads();

    // ---- Q fragments (held across both branches) ----
    uint32_t qh[4][4], ql[4][4];
#pragma unroll
    for (int ks = 0; ks < 4; ks++) {
        uint32_t ad = smb + AT_QHI + (wq0 + lrow) * KROW + ks * 32 + lhalf;
        ldm4(qh[ks], ad);
        ldm4(ql[ks], ad + (AT_QLO - AT_QHI));
    }

    float O[8][4];
#pragma unroll
    for (int i = 0; i < 8; i++)
#pragma unroll
        for (int e = 0; e < 4; e++) O[i][e] = 0.f;

    // ======================= branch 0: text (77 j, pad 80) =======================
    {
        // K tile (zero-pad rows >= 77)
        for (int i = tid; i < 640; i += 256) {
            int row = i >> 3, seg = i & 7;
            uint4 vh = make_uint4(0, 0, 0, 0), vl = vh;
            if (row < Ltxt) {
                size_t off = ((size_t)(b * Ltxt + row)) * Dm + hd * 64 + seg * 8;
                vh = *(const uint4*)(g_KVhi[0] + off);
                vl = *(const uint4*)(g_KVlo[0] + off);
            }
            *(uint4*)(sm + AT_KHI + row * KROW + seg * 16) = vh;
            *(uint4*)(sm + AT_KLO + row * KROW + seg * 16) = vl;
        }
        __syncthreads();

        float S[10][4];
#pragma unroll
        for (int t = 0; t < 10; t++)
#pragma unroll
            for (int e = 0; e < 4; e++) S[t][e] = 0.f;

#pragma unroll
        for (int np = 0; np < 5; np++)
#pragma unroll
            for (int ks = 0; ks < 4; ks++) {
                uint32_t bh[4], bl[4];
                uint32_t ad = smb + AT_KHI + (np * 16 + lrow) * KROW + ks * 32 + lhalf;
                ldm4(bh, ad);
                ldm4(bl, ad + (AT_KLO - AT_KHI));
#pragma unroll
                for (int q = 0; q < 2; q++) {
                    int t = np * 2 + q;
                    mma16816(S[t], qh[ks], bh[q], bh[q + 2]);
                    mma16816(S[t], qh[ks], bl[q], bl[q + 2]);
                    mma16816(S[t], ql[ks], bh[q], bh[q + 2]);
                }
            }

        // scale, mask, softmax (rows tg and tg+8)
#pragma unroll
        for (int t = 0; t < 10; t++)
#pragma unroll
            for (int e = 0; e < 4; e++) S[t][e] *= 0.125f;
        if (tq == 3) { S[9][0] = -1e30f; S[9][2] = -1e30f; }
        if (tq >= 2) { S[9][1] = -1e30f; S[9][3] = -1e30f; }

        float mx0 = -1e30f, mx1 = -1e30f;
#pragma unroll
        for (int t = 0; t < 10; t++) {
            mx0 = fmaxf(mx0, fmaxf(S[t][0], S[t][1]));
            mx1 = fmaxf(mx1, fmaxf(S[t][2], S[t][3]));
        }
        mx0 = fmaxf(mx0, __shfl_xor_sync(0xffffffffu, mx0, 1));
        mx0 = fmaxf(mx0, __shfl_xor_sync(0xffffffffu, mx0, 2));
        mx1 = fmaxf(mx1, __shfl_xor_sync(0xffffffffu, mx1, 1));
        mx1 = fmaxf(mx1, __shfl_xor_sync(0xffffffffu, mx1, 2));
        float s0 = 0.f, s1 = 0.f;
#pragma unroll
        for (int t = 0; t < 10; t++) {
            S[t][0] = __expf(S[t][0] - mx0); S[t][1] = __expf(S[t][1] - mx0);
            S[t][2] = __expf(S[t][2] - mx1); S[t][3] = __expf(S[t][3] - mx1);
            s0 += S[t][0] + S[t][1];
            s1 += S[t][2] + S[t][3];
        }
        s0 += __shfl_xor_sync(0xffffffffu, s0, 1);
        s0 += __shfl_xor_sync(0xffffffffu, s0, 2);
        s1 += __shfl_xor_sync(0xffffffffu, s1, 1);
        s1 += __shfl_xor_sync(0xffffffffu, s1, 2);
        float inv0 = 1.f / s0, inv1 = 1.f / s1;

        uint32_t phi[5][4], plo[5][4];
#pragma unroll
        for (int kj = 0; kj < 5; kj++) {
            int t0 = 2 * kj, t1 = 2 * kj + 1;
            sp2(S[t0][0] * inv0, S[t0][1] * inv0, phi[kj][0], plo[kj][0]);
            sp2(S[t0][2] * inv1, S[t0][3] * inv1, phi[kj][1], plo[kj][1]);
            sp2(S[t1][0] * inv0, S[t1][1] * inv0, phi[kj][2], plo[kj][2]);
            sp2(S[t1][2] * inv1, S[t1][3] * inv1, phi[kj][3], plo[kj][3]);
        }
        __syncthreads();   // K reads done

        // V tile (zero-pad rows >= 77; overwrites K region)
        for (int i = tid; i < 640; i += 256) {
            int row = i >> 3, seg = i & 7;
            uint4 vh = make_uint4(0, 0, 0, 0), vl = vh;
            if (row < Ltxt) {
                size_t off = ((size_t)(b * Ltxt + row)) * Dm + hd * 64 + seg * 8;
                vh = *(const uint4*)(g_KVhi[1] + off);
                vl = *(const uint4*)(g_KVlo[1] + off);
            }
            *(uint4*)(sm + AT_KHI + row * KROW + seg * 16) = vh;
            *(uint4*)(sm + AT_KLO + row * KROW + seg * 16) = vl;
        }
        __syncthreads();

        // PV: O += P @ V  (k = 80 j in 5 steps)
#pragma unroll
        for (int kj = 0; kj < 5; kj++) {
            int vrow = kj * 16 + ((lane >> 3) & 1) * 8 + (lane & 7);
#pragma unroll
            for (int ndp = 0; ndp < 4; ndp++) {
                uint32_t vh[4], vl[4];
                uint32_t ad = smb + AT_KHI + vrow * KROW +
                              (ndp * 2 + (lane >> 4)) * 16;
                ldm4t(vh, ad);
                ldm4t(vl, ad + (AT_KLO - AT_KHI));
                mma16816(O[ndp * 2],     phi[kj], vh[0], vh[1]);
                mma16816(O[ndp * 2],     phi[kj], vl[0], vl[1]);
                mma16816(O[ndp * 2],     plo[kj], vh[0], vh[1]);
                mma16816(O[ndp * 2 + 1], phi[kj], vh[2], vh[3]);
                mma16816(O[ndp * 2 + 1], phi[kj], vl[2], vl[3]);
                mma16816(O[ndp * 2 + 1], plo[kj], vh[2], vh[3]);
            }
        }
        __syncthreads();   // V region free for merged branch
    }

    // =============== branch 1: merged id (j 0-15) | hair (j 16-31) ===============
    {
        // K merged
        {
            int i = tid;                 // exactly 256 = 32 rows x 8 segs
            int row = i >> 3, seg = i & 7;
            int src_z = (row < 16) ? 2 : 4;
            int r = (row < 16) ? row : row - 16;
            size_t off = ((size_t)(b * Limg + r)) * Dm + hd * 64 + seg * 8;
            *(uint4*)(sm + AT_KHI + row * KROW + seg * 16) =
                *(const uint4*)(g_KVhi[src_z] + off);
            *(uint4*)(sm + AT_KLO + row * KROW + seg * 16) =
                *(const uint4*)(g_KVlo[src_z] + off);
        }
        __syncthreads();

        float S[4][4];
#pragma unroll
        for (int t = 0; t < 4; t++)
#pragma unroll
            for (int e = 0; e < 4; e++) S[t][e] = 0.f;

#pragma unroll
        for (int np = 0; np < 2; np++)
#pragma unroll
            for (int ks = 0; ks < 4; ks++) {
                uint32_t bh[4], bl[4];
                uint32_t ad = smb + AT_KHI + (np * 16 + lrow) * KROW + ks * 32 + lhalf;
                ldm4(bh, ad);
                ldm4(bl, ad + (AT_KLO - AT_KHI));
#pragma unroll
                for (int q = 0; q < 2; q++) {
                    int t = np * 2 + q;
                    mma16816(S[t], qh[ks], bh[q], bh[q + 2]);
                    mma16816(S[t], qh[ks], bl[q], bl[q + 2]);
                    mma16816(S[t], ql[ks], bh[q], bh[q + 2]);
                }
            }

#pragma unroll
        for (int t = 0; t < 4; t++)
#pragma unroll
            for (int e = 0; e < 4; e++) S[t][e] *= 0.125f;

        uint32_t phi[2][4], plo[2][4];
        // two independent softmaxes: half hf over tiles {2hf, 2hf+1}
#pragma unroll
        for (int hf = 0; hf < 2; hf++) {
            int ta = 2 * hf, tb = 2 * hf + 1;
            float mx0 = fmaxf(fmaxf(S[ta][0], S[ta][1]), fmaxf(S[tb][0], S[tb][1]));
            float mx1 = fmaxf(fmaxf(S[ta][2], S[ta][3]), fmaxf(S[tb][2], S[tb][3]));
            mx0 = fmaxf(mx0, __shfl_xor_sync(0xffffffffu, mx0, 1));
            mx0 = fmaxf(mx0, __shfl_xor_sync(0xffffffffu, mx0, 2));
            mx1 = fmaxf(mx1, __shfl_xor_sync(0xffffffffu, mx1, 1));
            mx1 = fmaxf(mx1, __shfl_xor_sync(0xffffffffu, mx1, 2));
            float e00 = __expf(S[ta][0] - mx0), e01 = __expf(S[ta][1] - mx0);
            float e02 = __expf(S[ta][2] - mx1), e03 = __expf(S[ta][3] - mx1);
            float e10 = __expf(S[tb][0] - mx0), e11 = __expf(S[tb][1] - mx0);
            float e12 = __expf(S[tb][2] - mx1), e13 = __expf(S[tb][3] - mx1);
            float s0 = e00 + e01 + e10 + e11;
            float s1 = e02 + e03 + e12 + e13;
            s0 += __shfl_xor_sync(0xffffffffu, s0, 1);
            s0 += __shfl_xor_sync(0xffffffffu, s0, 2);
            s1 += __shfl_xor_sync(0xffffffffu, s1, 1);
            s1 += __shfl_xor_sync(0xffffffffu, s1, 2);
            float inv0 = 1.f / s0, inv1 = 1.f / s1;
            sp2(e00 * inv0, e01 * inv0, phi[hf][0], plo[hf][0]);
            sp2(e02 * inv1, e03 * inv1, phi[hf][1], plo[hf][1]);
            sp2(e10 * inv0, e11 * inv0, phi[hf][2], plo[hf][2]);
            sp2(e12 * inv1, e13 * inv1, phi[hf][3], plo[hf][3]);
        }
        __syncthreads();

        // V merged
        {
            int i = tid;
            int row = i >> 3, seg = i & 7;
            int src_z = (row < 16) ? 3 : 5;
            int r = (row < 16) ? row : row - 16;
            size_t off = ((size_t)(b * Limg + r)) * Dm + hd * 64 + seg * 8;
            *(uint4*)(sm + AT_KHI + row * KROW + seg * 16) =
                *(const uint4*)(g_KVhi[src_z] + off);
            *(uint4*)(sm + AT_KLO + row * KROW + seg * 16) =
                *(const uint4*)(g_KVlo[src_z] + off);
        }
        __syncthreads();

#pragma unroll
        for (int kj = 0; kj < 2; kj++) {
            int vrow = kj * 16 + ((lane >> 3) & 1) * 8 + (lane & 7);
#pragma unroll
            for (int ndp = 0; ndp < 4; ndp++) {
                uint32_t vh[4], vl[4];
                uint32_t ad = smb + AT_KHI + vrow * KROW +
                              (ndp * 2 + (lane >> 4)) * 16;
                ldm4t(vh, ad);
                ldm4t(vl, ad + (AT_KLO - AT_KHI));
                mma16816(O[ndp * 2],     phi[kj], vh[0], vh[1]);
                mma16816(O[ndp * 2],     phi[kj], vl[0], vl[1]);
                mma16816(O[ndp * 2],     plo[kj], vh[0], vh[1]);
                mma16816(O[ndp * 2 + 1], phi[kj], vh[2], vh[3]);
                mma16816(O[ndp * 2 + 1], phi[kj], vl[2], vl[3]);
                mma16816(O[ndp * 2 + 1], plo[kj], vh[2], vh[3]);
            }
        }
    }

    // ---- epilogue: split O to bf16 hi/lo for the out-GEMM ----
    {
        size_t r0 = (size_t)(b * Sq + q0 + wq0 + tg) * Dm + hd * 64 + tq * 2;
        size_t r1 = r0 + 8 * (size_t)Dm;
#pragma unroll
        for (int nd = 0; nd < 8; nd++) {
            uint32_t h, l;
            sp2(O[nd][0], O[nd][1], h, l);
            *(uint32_t*)(g_Ohi + r0 + nd * 8) = h;
            *(uint32_t*)(g_Olo + r0 + nd * 8) = l;
            sp2(O[nd][2], O[nd][3], h, l);
            *(uint32_t*)(g_Ohi + r1 + nd * 8) = h;
            *(uint32_t*)(g_Olo + r1 + nd * 8) = l;
        }
    }
}

// ---------------------------------------------------------------------------
// kernel_launch
// ---------------------------------------------------------------------------
extern "C" void kernel_launch(void* const* d_in, const int* in_sizes, int n_in,
                              void* d_out, int out_size) {
    const float* hidden = (const float*)d_in[0];
    const float* text   = (const float*)d_in[1];
    const float* ids    = (const float*)d_in[2];
    const float* hair   = (const float*)d_in[3];
    const float* Wq     = (const float*)d_in[4];
    const float* Wk     = (const float*)d_in[5];
    const float* Wv     = (const float*)d_in[6];
    const float* Wo     = (const float*)d_in[7];
    const float* bo     = (const float*)d_in[8];
    const float* Wk_id  = (const float*)d_in[9];
    const float* Wv_id  = (const float*)d_in[10];
    const float* Wk_h   = (const float*)d_in[11];
    const float* Wv_h   = (const float*)d_in[12];
    float* out = (float*)d_out;

    cudaFuncSetAttribute(gemm_qkv_kernel, cudaFuncAttributeMaxDynamicSharedMemorySize, GSMEM);
    cudaFuncSetAttribute(gemm_out_kernel, cudaFuncAttributeMaxDynamicSharedMemorySize, GSMEM);
    cudaFuncSetAttribute(attn_kernel,     cudaFuncAttributeMaxDynamicSharedMemorySize, AT_SMEM);

    // 1) transpose + split all 8 weight matrices -> Wt[n][k] hi/lo
    transpose_split_kernel<<<dim3(Dm / 32, Cm / 32, 8), 256>>>(
        Wq, Wo, Wk, Wv, Wk_id, Wv_id, Wk_h, Wv_h);

    // 2) split activations -> hi/lo bf16
    split_inputs_kernel<<<dim3(8192, 1, 4), 256>>>(hidden, text, ids, hair);

    // 3) Q GEMM + all six K/V projections in ONE launch (split-bf16 outputs)
    gemm_qkv_kernel<<<dim3(Dm / BN, 256 + 14), 256, GSMEM>>>();

    // 4) flash-style MMA attention -> g_Ohi/g_Olo
    attn_kernel<<<dim3(Sq / 128, Bsz * Hh), 256, AT_SMEM>>>();

    // 5) out = O @ Wo + bo
    gemm_out_kernel<<<dim3(Dm / BN, Mbig / BM), 256, GSMEM>>>(bo, out);
}